// round 1
// baseline (speedup 1.0000x reference)
#include <cuda_runtime.h>
#include <math.h>

#define N_NODES 8192
#define D_DIM   512
#define E_EDGES 262144

// Scratch (allocation-free rule: device globals)
__device__ float g_bufA[N_NODES * D_DIM];  // layer-2 output / emb
__device__ float g_bufB[N_NODES * D_DIM];  // agg buffer
__device__ float g_bufC[N_NODES * D_DIM];  // layer-1 output
__device__ float g_inv[N_NODES];           // 1/(rowsum+1e-4)

// ---------------------------------------------------------------------------
// rowsum reciprocal: one block (128 threads) per row, D=512 -> 1 float4/thread
__global__ void rowsum_inv_kernel(const float* __restrict__ x,
                                  float* __restrict__ inv) {
    int row = blockIdx.x;
    const float4 v = reinterpret_cast<const float4*>(x)[row * (D_DIM / 4) + threadIdx.x];
    float s = v.x + v.y + v.z + v.w;
    #pragma unroll
    for (int o = 16; o > 0; o >>= 1) s += __shfl_down_sync(0xffffffffu, s, o);
    __shared__ float red[4];
    if ((threadIdx.x & 31) == 0) red[threadIdx.x >> 5] = s;
    __syncthreads();
    if (threadIdx.x == 0) {
        float t = red[0] + red[1] + red[2] + red[3];
        inv[row] = 1.0f / (t + 1e-4f);
    }
}

// ---------------------------------------------------------------------------
__global__ void zero_kernel(float* __restrict__ p, int n4) {
    float4 z = make_float4(0.f, 0.f, 0.f, 0.f);
    for (int i = blockIdx.x * blockDim.x + threadIdx.x; i < n4; i += gridDim.x * blockDim.x)
        reinterpret_cast<float4*>(p)[i] = z;
}

// ---------------------------------------------------------------------------
// SpMM scatter: agg[row[e]] += w[e] * inv[col[e]] * x[col[e]]
// 128 threads per edge (1 float4 each), 2 edges per 256-thread block.
__global__ void spmm_kernel(const float* __restrict__ x,
                            const float* __restrict__ inv,
                            const int* __restrict__ ei,
                            const float* __restrict__ ew,
                            float* __restrict__ agg) {
    int e = blockIdx.x * 2 + (threadIdx.x >> 7);
    int t = threadIdx.x & 127;
    int dst = ei[e];              // edge_index[0] = row (dest)
    int src = ei[E_EDGES + e];    // edge_index[1] = col (source)
    float s = ew[e] * inv[src];
    float4 v = reinterpret_cast<const float4*>(x)[src * (D_DIM / 4) + t];
    float* o = agg + (size_t)dst * D_DIM + t * 4;
    atomicAdd(o + 0, s * v.x);
    atomicAdd(o + 1, s * v.y);
    atomicAdd(o + 2, s * v.z);
    atomicAdd(o + 3, s * v.w);
}

// ---------------------------------------------------------------------------
// NT SGEMM: C[M,N] = A[M,K] * B[N,K]^T, both row-major with K contiguous.
// 128x128 tile, BK=16, 256 threads, 8x8 micro-tile per thread (split 4+4).
// mode 0: elu(z + bias[col]);  mode 1: relu(z)
__global__ __launch_bounds__(256, 2)
void sgemm_nt_kernel(const float* __restrict__ A, const float* __restrict__ B,
                     const float* __restrict__ bias, float* __restrict__ C,
                     int M, int Nn, int K, int mode) {
    const int BM = 128, BN = 128, BK = 16;
    __shared__ float As[BK][BM];
    __shared__ float Bs[BK][BN];

    int tid = threadIdx.x;
    int tm = tid >> 4;   // 0..15
    int tn = tid & 15;   // 0..15
    int lr = tid >> 2;   // 0..63 (loader row)
    int lc = tid & 3;    // 0..3  (loader float4 col)
    int row0 = blockIdx.y * BM;
    int col0 = blockIdx.x * BN;

    float acc[8][8];
    #pragma unroll
    for (int i = 0; i < 8; i++)
        #pragma unroll
        for (int j = 0; j < 8; j++) acc[i][j] = 0.f;

    const float* Ag = A + (size_t)row0 * K;
    const float* Bg = B + (size_t)col0 * K;

    for (int kt = 0; kt < K; kt += BK) {
        #pragma unroll
        for (int it = 0; it < 2; it++) {
            int m = lr + it * 64;
            float4 av = *reinterpret_cast<const float4*>(Ag + (size_t)m * K + kt + lc * 4);
            As[lc * 4 + 0][m] = av.x; As[lc * 4 + 1][m] = av.y;
            As[lc * 4 + 2][m] = av.z; As[lc * 4 + 3][m] = av.w;
            float4 bv = *reinterpret_cast<const float4*>(Bg + (size_t)m * K + kt + lc * 4);
            Bs[lc * 4 + 0][m] = bv.x; Bs[lc * 4 + 1][m] = bv.y;
            Bs[lc * 4 + 2][m] = bv.z; Bs[lc * 4 + 3][m] = bv.w;
        }
        __syncthreads();
        #pragma unroll
        for (int k = 0; k < BK; k++) {
            float4 a0 = *reinterpret_cast<const float4*>(&As[k][tm * 4]);
            float4 a1 = *reinterpret_cast<const float4*>(&As[k][64 + tm * 4]);
            float4 b0 = *reinterpret_cast<const float4*>(&Bs[k][tn * 4]);
            float4 b1 = *reinterpret_cast<const float4*>(&Bs[k][64 + tn * 4]);
            float a[8] = {a0.x, a0.y, a0.z, a0.w, a1.x, a1.y, a1.z, a1.w};
            float b[8] = {b0.x, b0.y, b0.z, b0.w, b1.x, b1.y, b1.z, b1.w};
            #pragma unroll
            for (int i = 0; i < 8; i++)
                #pragma unroll
                for (int j = 0; j < 8; j++)
                    acc[i][j] = fmaf(a[i], b[j], acc[i][j]);
        }
        __syncthreads();
    }

    // epilogue
    #pragma unroll
    for (int i = 0; i < 8; i++) {
        int r = row0 + ((i < 4) ? (tm * 4 + i) : (64 + tm * 4 + i - 4));
        #pragma unroll
        for (int jh = 0; jh < 2; jh++) {
            int c = col0 + (jh ? (64 + tn * 4) : (tn * 4));
            float4 v;
            float* pv = &v.x;
            #pragma unroll
            for (int j = 0; j < 4; j++) {
                float z = acc[i][jh * 4 + j];
                if (mode == 0) {
                    z += bias[c + j];
                    z = (z > 0.f) ? z : (expm1f(z));
                } else {
                    z = (z > 0.f) ? z : 0.f;
                }
                pv[j] = z;
            }
            *reinterpret_cast<float4*>(C + (size_t)r * Nn + c) = v;
        }
    }
}

// ---------------------------------------------------------------------------
// In-place L2 row normalization: emb = x / max(||x||, 1e-12)
__global__ void l2norm_kernel(float* __restrict__ x) {
    int row = blockIdx.x;
    float4* xr = reinterpret_cast<float4*>(x) + row * (D_DIM / 4);
    float4 v = xr[threadIdx.x];
    float s = v.x * v.x + v.y * v.y + v.z * v.z + v.w * v.w;
    #pragma unroll
    for (int o = 16; o > 0; o >>= 1) s += __shfl_down_sync(0xffffffffu, s, o);
    __shared__ float red[4];
    __shared__ float sscale;
    if ((threadIdx.x & 31) == 0) red[threadIdx.x >> 5] = s;
    __syncthreads();
    if (threadIdx.x == 0) {
        float t = red[0] + red[1] + red[2] + red[3];
        float nrm = sqrtf(t);
        sscale = 1.0f / fmaxf(nrm, 1e-12f);
    }
    __syncthreads();
    float sc = sscale;
    v.x *= sc; v.y *= sc; v.z *= sc; v.w *= sc;
    xr[threadIdx.x] = v;
}

// ---------------------------------------------------------------------------
extern "C" void kernel_launch(void* const* d_in, const int* in_sizes, int n_in,
                              void* d_out, int out_size) {
    const float* x  = (const float*)d_in[0];
    const int*   ei = (const int*)d_in[1];
    const float* ew = (const float*)d_in[2];
    const float* W  = (const float*)d_in[3];
    const float* b  = (const float*)d_in[4];
    float* out = (float*)d_out;

    float *A, *B, *C, *inv;
    cudaGetSymbolAddress((void**)&A, g_bufA);
    cudaGetSymbolAddress((void**)&B, g_bufB);
    cudaGetSymbolAddress((void**)&C, g_bufC);
    cudaGetSymbolAddress((void**)&inv, g_inv);

    dim3 gSmall(D_DIM / 128, N_NODES / 128);   // 4 x 64
    dim3 gBig(N_NODES / 128, N_NODES / 128);   // 64 x 64

    // ---- layer 1 ----
    rowsum_inv_kernel<<<N_NODES, 128>>>(x, inv);
    zero_kernel<<<2048, 256>>>(B, N_NODES * D_DIM / 4);
    spmm_kernel<<<E_EDGES / 2, 256>>>(x, inv, ei, ew, B);
    sgemm_nt_kernel<<<gSmall, 256>>>(B, W, b, C, N_NODES, D_DIM, D_DIM, 0);

    // ---- layer 2 ----
    rowsum_inv_kernel<<<N_NODES, 128>>>(C, inv);
    zero_kernel<<<2048, 256>>>(B, N_NODES * D_DIM / 4);
    spmm_kernel<<<E_EDGES / 2, 256>>>(C, inv, ei, ew, B);
    sgemm_nt_kernel<<<gSmall, 256>>>(B, W, b, A, N_NODES, D_DIM, D_DIM, 0);

    // ---- normalize + similarity ----
    l2norm_kernel<<<N_NODES, 128>>>(A);
    sgemm_nt_kernel<<<gBig, 256>>>(A, A, nullptr, out, N_NODES, N_NODES, D_DIM, 1);
}

// round 3
// speedup vs baseline: 1.9652x; 1.9652x over previous
#include <cuda_runtime.h>
#include <cuda_bf16.h>
#include <math.h>
#include <stdint.h>

#define N_NODES 8192
#define D_DIM   512
#define E_EDGES 262144

// Scratch (allocation-free rule: device globals)
__device__ float g_bufA[N_NODES * D_DIM];  // layer-2 output / emb (f32)
__device__ float g_bufB[N_NODES * D_DIM];  // agg buffer
__device__ float g_bufC[N_NODES * D_DIM];  // layer-1 output
__device__ float g_inv[N_NODES];           // 1/(rowsum+1e-4)
__device__ __nv_bfloat16 g_hi[N_NODES * D_DIM];  // split-bf16 high
__device__ __nv_bfloat16 g_lo[N_NODES * D_DIM];  // split-bf16 low

// ============================ PTX helpers (base PTX only!) =================
__device__ __forceinline__ uint32_t smem_u32(const void* p) {
    uint32_t a;
    asm("{ .reg .u64 t; cvta.to.shared.u64 t, %1; cvt.u32.u64 %0, t; }"
        : "=r"(a) : "l"(p));
    return a;
}
#define CPA16(s, g) \
    asm volatile("cp.async.cg.shared.global [%0], [%1], 16;" :: "r"(s), "l"(g))
#define CPA_COMMIT() asm volatile("cp.async.commit_group;" ::: "memory")

__device__ __forceinline__ void ldm_x4(uint32_t* r, uint32_t addr) {
    asm volatile("ldmatrix.sync.aligned.m8n8.x4.shared.b16 {%0,%1,%2,%3}, [%4];"
                 : "=r"(r[0]), "=r"(r[1]), "=r"(r[2]), "=r"(r[3]) : "r"(addr));
}
__device__ __forceinline__ void mma_bf16(float* c, const uint32_t* a,
                                         const uint32_t* b) {
    asm volatile(
        "mma.sync.aligned.m16n8k16.row.col.f32.bf16.bf16.f32 "
        "{%0,%1,%2,%3}, {%4,%5,%6,%7}, {%8,%9}, {%0,%1,%2,%3};"
        : "+f"(c[0]), "+f"(c[1]), "+f"(c[2]), "+f"(c[3])
        : "r"(a[0]), "r"(a[1]), "r"(a[2]), "r"(a[3]), "r"(b[0]), "r"(b[1]));
}

// ============================ small kernels ================================
__global__ void rowsum_inv_kernel(const float* __restrict__ x,
                                  float* __restrict__ inv) {
    int row = blockIdx.x;
    const float4 v = reinterpret_cast<const float4*>(x)[row * (D_DIM / 4) + threadIdx.x];
    float s = v.x + v.y + v.z + v.w;
    #pragma unroll
    for (int o = 16; o > 0; o >>= 1) s += __shfl_down_sync(0xffffffffu, s, o);
    __shared__ float red[4];
    if ((threadIdx.x & 31) == 0) red[threadIdx.x >> 5] = s;
    __syncthreads();
    if (threadIdx.x == 0) {
        float t = red[0] + red[1] + red[2] + red[3];
        inv[row] = 1.0f / (t + 1e-4f);
    }
}

__global__ void zero_kernel(float* __restrict__ p, int n4) {
    float4 z = make_float4(0.f, 0.f, 0.f, 0.f);
    for (int i = blockIdx.x * blockDim.x + threadIdx.x; i < n4; i += gridDim.x * blockDim.x)
        reinterpret_cast<float4*>(p)[i] = z;
}

__global__ void spmm_kernel(const float* __restrict__ x,
                            const float* __restrict__ inv,
                            const int* __restrict__ ei,
                            const float* __restrict__ ew,
                            float* __restrict__ agg) {
    int e = blockIdx.x * 2 + (threadIdx.x >> 7);
    int t = threadIdx.x & 127;
    int dst = ei[e];
    int src = ei[E_EDGES + e];
    float s = ew[e] * inv[src];
    float4 v = reinterpret_cast<const float4*>(x)[src * (D_DIM / 4) + t];
    float* o = agg + (size_t)dst * D_DIM + t * 4;
    atomicAdd(o + 0, s * v.x);
    atomicAdd(o + 1, s * v.y);
    atomicAdd(o + 2, s * v.z);
    atomicAdd(o + 3, s * v.w);
}

// SIMT NT SGEMM for the two D=512 layer GEMMs (elu + bias epilogue)
__global__ __launch_bounds__(256, 2)
void sgemm_nt_kernel(const float* __restrict__ A, const float* __restrict__ B,
                     const float* __restrict__ bias, float* __restrict__ C,
                     int M, int Nn, int K) {
    const int BMt = 128, BK = 16;
    __shared__ float As[BK][BMt];
    __shared__ float Bs[BK][BMt];

    int tid = threadIdx.x;
    int tm = tid >> 4, tn = tid & 15;
    int lr = tid >> 2, lc = tid & 3;
    int row0 = blockIdx.y * BMt;
    int col0 = blockIdx.x * BMt;

    float acc[8][8];
    #pragma unroll
    for (int i = 0; i < 8; i++)
        #pragma unroll
        for (int j = 0; j < 8; j++) acc[i][j] = 0.f;

    const float* Ag = A + (size_t)row0 * K;
    const float* Bg = B + (size_t)col0 * K;

    for (int kt = 0; kt < K; kt += BK) {
        #pragma unroll
        for (int it = 0; it < 2; it++) {
            int m = lr + it * 64;
            float4 av = *reinterpret_cast<const float4*>(Ag + (size_t)m * K + kt + lc * 4);
            As[lc * 4 + 0][m] = av.x; As[lc * 4 + 1][m] = av.y;
            As[lc * 4 + 2][m] = av.z; As[lc * 4 + 3][m] = av.w;
            float4 bv = *reinterpret_cast<const float4*>(Bg + (size_t)m * K + kt + lc * 4);
            Bs[lc * 4 + 0][m] = bv.x; Bs[lc * 4 + 1][m] = bv.y;
            Bs[lc * 4 + 2][m] = bv.z; Bs[lc * 4 + 3][m] = bv.w;
        }
        __syncthreads();
        #pragma unroll
        for (int k = 0; k < BK; k++) {
            float4 a0 = *reinterpret_cast<const float4*>(&As[k][tm * 4]);
            float4 a1 = *reinterpret_cast<const float4*>(&As[k][64 + tm * 4]);
            float4 b0 = *reinterpret_cast<const float4*>(&Bs[k][tn * 4]);
            float4 b1 = *reinterpret_cast<const float4*>(&Bs[k][64 + tn * 4]);
            float a[8] = {a0.x, a0.y, a0.z, a0.w, a1.x, a1.y, a1.z, a1.w};
            float b[8] = {b0.x, b0.y, b0.z, b0.w, b1.x, b1.y, b1.z, b1.w};
            #pragma unroll
            for (int i = 0; i < 8; i++)
                #pragma unroll
                for (int j = 0; j < 8; j++)
                    acc[i][j] = fmaf(a[i], b[j], acc[i][j]);
        }
        __syncthreads();
    }

    #pragma unroll
    for (int i = 0; i < 8; i++) {
        int r = row0 + ((i < 4) ? (tm * 4 + i) : (64 + tm * 4 + i - 4));
        #pragma unroll
        for (int jh = 0; jh < 2; jh++) {
            int c = col0 + (jh ? (64 + tn * 4) : (tn * 4));
            float4 v;
            float* pv = &v.x;
            #pragma unroll
            for (int j = 0; j < 4; j++) {
                float z = acc[i][jh * 4 + j] + bias[c + j];
                pv[j] = (z > 0.f) ? z : expm1f(z);
            }
            *reinterpret_cast<float4*>(C + (size_t)r * Nn + c) = v;
        }
    }
}

// L2 normalize rows of x and emit split-bf16 (hi + lo ~= x_normalized)
__global__ void l2norm_split_kernel(const float* __restrict__ x,
                                    __nv_bfloat16* __restrict__ hi,
                                    __nv_bfloat16* __restrict__ lo) {
    int row = blockIdx.x;
    const float4 v = reinterpret_cast<const float4*>(x)[row * (D_DIM / 4) + threadIdx.x];
    float s = v.x * v.x + v.y * v.y + v.z * v.z + v.w * v.w;
    #pragma unroll
    for (int o = 16; o > 0; o >>= 1) s += __shfl_down_sync(0xffffffffu, s, o);
    __shared__ float red[4];
    __shared__ float sscale;
    if ((threadIdx.x & 31) == 0) red[threadIdx.x >> 5] = s;
    __syncthreads();
    if (threadIdx.x == 0) {
        float t = red[0] + red[1] + red[2] + red[3];
        sscale = 1.0f / fmaxf(sqrtf(t), 1e-12f);
    }
    __syncthreads();
    float sc = sscale;
    float a[4] = {v.x * sc, v.y * sc, v.z * sc, v.w * sc};
    int base = row * D_DIM + threadIdx.x * 4;
    #pragma unroll
    for (int i = 0; i < 4; i++) {
        __nv_bfloat16 h = __float2bfloat16(a[i]);
        hi[base + i] = h;
        lo[base + i] = __float2bfloat16(a[i] - __bfloat162float(h));
    }
}

// ==================== mma.sync similarity GEMM (symmetric) =================
// out = relu(emb @ emb^T). Only lower-triangular 128x128 blocks computed;
// mirrored through padded smem. Split-bf16: hi*hi^T + hi*lo^T + lo*hi^T.
//
// CTA: 256 threads = 8 warps (2 x 4), warp tile 64x32.
// K chunk = 32 bf16 (64B/row), smem rows padded to 80B (conflict-free ldmatrix).
#define SIM_BM 128
#define SIM_KC 32
#define ROWB   80                       // padded row stride (bytes)
#define OPSZ   (SIM_BM * ROWB)          // 10240 B per operand tile
#define STG    (4 * OPSZ)               // Ahi,Alo,Bhi,Blo per stage: 40960 B
#define SIM_SMEM (2 * STG)              // 81920 B (epilogue reuses: 66048 B)
#define NCHUNK (D_DIM / SIM_KC)         // 16

__global__ __launch_bounds__(256)
void sim_mma_kernel(const __nv_bfloat16* __restrict__ hi,
                    const __nv_bfloat16* __restrict__ lo,
                    float* __restrict__ out) {
    extern __shared__ char smem[];
    const uint32_t sb = smem_u32(smem);
    const int tid = threadIdx.x;
    const int wid = tid >> 5, lane = tid & 31;
    const int wm = wid >> 2, wn = wid & 3;      // 2 x 4 warp grid

    // triangular block decode
    int k = blockIdx.x;
    int bi = (int)((sqrtf(8.f * (float)k + 1.f) - 1.f) * 0.5f);
    while ((bi + 1) * (bi + 2) / 2 <= k) bi++;
    while (bi * (bi + 1) / 2 > k) bi--;
    int bj = k - bi * (bi + 1) / 2;
    const int row0 = bi * SIM_BM, col0 = bj * SIM_BM;

    const __nv_bfloat16* gA[2] = { hi + (size_t)row0 * D_DIM, lo + (size_t)row0 * D_DIM };
    const __nv_bfloat16* gB[2] = { hi + (size_t)col0 * D_DIM, lo + (size_t)col0 * D_DIM };

    float acc[4][4][4];   // [mi][nj][frag]
    #pragma unroll
    for (int i = 0; i < 4; i++)
        #pragma unroll
        for (int j = 0; j < 4; j++)
            #pragma unroll
            for (int q = 0; q < 4; q++) acc[i][j][q] = 0.f;

    auto load_chunk = [&](int c) {
        uint32_t st = sb + (uint32_t)(c & 1) * STG;
        int koff = c * SIM_KC;
        #pragma unroll
        for (int h = 0; h < 2; h++) {   // hi, lo
            #pragma unroll
            for (int i = 0; i < 2; i++) {
                int idx = i * 256 + tid;            // 512 16B-chunks per operand
                int r = idx >> 2, cc = idx & 3;
                CPA16(st + (h)*OPSZ + r * ROWB + cc * 16,
                      gA[h] + (size_t)r * D_DIM + koff + cc * 8);
                CPA16(st + (2 + h) * OPSZ + r * ROWB + cc * 16,
                      gB[h] + (size_t)r * D_DIM + koff + cc * 8);
            }
        }
        CPA_COMMIT();
    };

    load_chunk(0);
    load_chunk(1);

    for (int c = 0; c < NCHUNK; c++) {
        if (c < NCHUNK - 1) asm volatile("cp.async.wait_group 1;" ::: "memory");
        else                asm volatile("cp.async.wait_group 0;" ::: "memory");
        __syncthreads();

        uint32_t st = sb + (uint32_t)(c & 1) * STG;
        #pragma unroll
        for (int ks = 0; ks < 2; ks++) {
            // A fragments (hi & lo): 4 m-tiles each
            uint32_t afr[2][4][4];
            {
                int rowA = wm * 64 + (lane & 15);
                int chk = 2 * ks + (lane >> 4);
                uint32_t off = (uint32_t)(rowA * ROWB + chk * 16);
                #pragma unroll
                for (int h = 0; h < 2; h++)
                    #pragma unroll
                    for (int mi = 0; mi < 4; mi++)
                        ldm_x4(afr[h][mi], st + h * OPSZ + off + (uint32_t)(mi * 16 * ROWB));
            }
            // B fragments (hi & lo): 4 n-tiles (two x4 loads each, 2 tiles/load)
            uint32_t bfr[2][4][2];
            {
                int rowB = wn * 32 + ((lane >> 4) & 1) * 8 + (lane & 7);
                int chk = 2 * ks + ((lane >> 3) & 1);
                uint32_t off = (uint32_t)(rowB * ROWB + chk * 16);
                #pragma unroll
                for (int h = 0; h < 2; h++)
                    #pragma unroll
                    for (int jp = 0; jp < 2; jp++) {
                        uint32_t r4[4];
                        ldm_x4(r4, st + (2 + h) * OPSZ + off + (uint32_t)(jp * 16 * ROWB));
                        bfr[h][jp * 2 + 0][0] = r4[0]; bfr[h][jp * 2 + 0][1] = r4[1];
                        bfr[h][jp * 2 + 1][0] = r4[2]; bfr[h][jp * 2 + 1][1] = r4[3];
                    }
            }
            #pragma unroll
            for (int mi = 0; mi < 4; mi++)
                #pragma unroll
                for (int nj = 0; nj < 4; nj++) {
                    mma_bf16(acc[mi][nj], afr[0][mi], bfr[0][nj]);  // hi*hi
                    mma_bf16(acc[mi][nj], afr[0][mi], bfr[1][nj]);  // hi*lo
                    mma_bf16(acc[mi][nj], afr[1][mi], bfr[0][nj]);  // lo*hi
                }
        }
        __syncthreads();
        if (c + 2 < NCHUNK) load_chunk(c + 2);
    }

    // -------- epilogue: acc -> padded smem -> relu -> out (+ mirror) --------
    __syncthreads();
    float* Csm = reinterpret_cast<float*>(smem);   // 128 x 129 floats
    #pragma unroll
    for (int mi = 0; mi < 4; mi++) {
        int r = wm * 64 + mi * 16 + (lane >> 2);
        #pragma unroll
        for (int nj = 0; nj < 4; nj++) {
            int cc = wn * 32 + nj * 8 + (lane & 3) * 2;
            Csm[r * 129 + cc]           = acc[mi][nj][0];
            Csm[r * 129 + cc + 1]       = acc[mi][nj][1];
            Csm[(r + 8) * 129 + cc]     = acc[mi][nj][2];
            Csm[(r + 8) * 129 + cc + 1] = acc[mi][nj][3];
        }
    }
    __syncthreads();

    #pragma unroll 4
    for (int i = 0; i < 64; i++) {
        int idx = i * 256 + tid;
        int r = idx >> 7, cc = idx & 127;
        float v = Csm[r * 129 + cc];
        v = (v > 0.f) ? v : 0.f;
        out[(size_t)(row0 + r) * N_NODES + col0 + cc] = v;
    }
    if (bi != bj) {
        #pragma unroll 4
        for (int i = 0; i < 64; i++) {
            int idx = i * 256 + tid;
            int rr = idx & 127, cc = idx >> 7;   // lane varies rr -> coalesced out
            float v = Csm[rr * 129 + cc];        // column read, stride 129: no conflicts
            v = (v > 0.f) ? v : 0.f;
            out[(size_t)(col0 + cc) * N_NODES + row0 + rr] = v;
        }
    }
}

// ===========================================================================
extern "C" void kernel_launch(void* const* d_in, const int* in_sizes, int n_in,
                              void* d_out, int out_size) {
    const float* x  = (const float*)d_in[0];
    const int*   ei = (const int*)d_in[1];
    const float* ew = (const float*)d_in[2];
    const float* W  = (const float*)d_in[3];
    const float* b  = (const float*)d_in[4];
    float* out = (float*)d_out;

    float *A, *B, *C, *inv;
    __nv_bfloat16 *hi, *lo;
    cudaGetSymbolAddress((void**)&A, g_bufA);
    cudaGetSymbolAddress((void**)&B, g_bufB);
    cudaGetSymbolAddress((void**)&C, g_bufC);
    cudaGetSymbolAddress((void**)&inv, g_inv);
    cudaGetSymbolAddress((void**)&hi, g_hi);
    cudaGetSymbolAddress((void**)&lo, g_lo);

    cudaFuncSetAttribute(sim_mma_kernel,
                         cudaFuncAttributeMaxDynamicSharedMemorySize, SIM_SMEM);

    dim3 gSmall(D_DIM / 128, N_NODES / 128);   // 4 x 64

    // ---- layer 1 ----
    rowsum_inv_kernel<<<N_NODES, 128>>>(x, inv);
    zero_kernel<<<2048, 256>>>(B, N_NODES * D_DIM / 4);
    spmm_kernel<<<E_EDGES / 2, 256>>>(x, inv, ei, ew, B);
    sgemm_nt_kernel<<<gSmall, 256>>>(B, W, b, C, N_NODES, D_DIM, D_DIM);

    // ---- layer 2 ----
    rowsum_inv_kernel<<<N_NODES, 128>>>(C, inv);
    zero_kernel<<<2048, 256>>>(B, N_NODES * D_DIM / 4);
    spmm_kernel<<<E_EDGES / 2, 256>>>(C, inv, ei, ew, B);
    sgemm_nt_kernel<<<gSmall, 256>>>(B, W, b, A, N_NODES, D_DIM, D_DIM);

    // ---- normalize + split to bf16 hi/lo ----
    l2norm_split_kernel<<<N_NODES, 128>>>(A, hi, lo);

    // ---- similarity: symmetric tiles, mma.sync split-bf16 + relu ----
    int nblk = (N_NODES / SIM_BM);             // 64
    int ntri = nblk * (nblk + 1) / 2;          // 2080
    sim_mma_kernel<<<ntri, 256, SIM_SMEM>>>(hi, lo, out);
}

// round 4
// speedup vs baseline: 3.3598x; 1.7096x over previous
#include <cuda_runtime.h>
#include <cuda_bf16.h>
#include <math.h>
#include <stdint.h>

#define N_NODES 8192
#define D_DIM   512
#define E_EDGES 262144

// Scratch (allocation-free rule: device globals)
__device__ float g_bufA[N_NODES * D_DIM];  // layer-2 output / emb (f32)
__device__ float g_bufB[N_NODES * D_DIM];  // agg buffer
__device__ float g_bufC[N_NODES * D_DIM];  // layer-1 output
__device__ float g_inv[N_NODES];           // 1/(rowsum+1e-4)
__device__ __nv_bfloat16 g_hi[N_NODES * D_DIM];  // split-bf16 high
__device__ __nv_bfloat16 g_lo[N_NODES * D_DIM];  // split-bf16 low
__device__ __nv_bfloat16 g_Whi[D_DIM * D_DIM];
__device__ __nv_bfloat16 g_Wlo[D_DIM * D_DIM];

// ============================ PTX helpers (base PTX only!) =================
__device__ __forceinline__ uint32_t smem_u32(const void* p) {
    uint32_t a;
    asm("{ .reg .u64 t; cvta.to.shared.u64 t, %1; cvt.u32.u64 %0, t; }"
        : "=r"(a) : "l"(p));
    return a;
}
#define CPA16(s, g) \
    asm volatile("cp.async.cg.shared.global [%0], [%1], 16;" :: "r"(s), "l"(g))
#define CPA_COMMIT() asm volatile("cp.async.commit_group;" ::: "memory")

__device__ __forceinline__ void ldm_x4(uint32_t* r, uint32_t addr) {
    asm volatile("ldmatrix.sync.aligned.m8n8.x4.shared.b16 {%0,%1,%2,%3}, [%4];"
                 : "=r"(r[0]), "=r"(r[1]), "=r"(r[2]), "=r"(r[3]) : "r"(addr));
}
__device__ __forceinline__ void mma_bf16(float* c, const uint32_t* a,
                                         const uint32_t* b) {
    asm volatile(
        "mma.sync.aligned.m16n8k16.row.col.f32.bf16.bf16.f32 "
        "{%0,%1,%2,%3}, {%4,%5,%6,%7}, {%8,%9}, {%0,%1,%2,%3};"
        : "+f"(c[0]), "+f"(c[1]), "+f"(c[2]), "+f"(c[3])
        : "r"(a[0]), "r"(a[1]), "r"(a[2]), "r"(a[3]), "r"(b[0]), "r"(b[1]));
}
__device__ __forceinline__ void redg_v4(float* addr, float a, float b,
                                        float c, float d) {
    asm volatile("red.global.add.v4.f32 [%0], {%1,%2,%3,%4};"
                 :: "l"(addr), "f"(a), "f"(b), "f"(c), "f"(d) : "memory");
}

// ============================ small kernels ================================
__global__ void rowsum_inv_kernel(const float* __restrict__ x,
                                  float* __restrict__ inv) {
    int row = blockIdx.x;
    const float4 v = reinterpret_cast<const float4*>(x)[row * (D_DIM / 4) + threadIdx.x];
    float s = v.x + v.y + v.z + v.w;
    #pragma unroll
    for (int o = 16; o > 0; o >>= 1) s += __shfl_down_sync(0xffffffffu, s, o);
    __shared__ float red[4];
    if ((threadIdx.x & 31) == 0) red[threadIdx.x >> 5] = s;
    __syncthreads();
    if (threadIdx.x == 0) {
        float t = red[0] + red[1] + red[2] + red[3];
        inv[row] = 1.0f / (t + 1e-4f);
    }
}

__global__ void zero_kernel(float* __restrict__ p, int n4) {
    float4 z = make_float4(0.f, 0.f, 0.f, 0.f);
    for (int i = blockIdx.x * blockDim.x + threadIdx.x; i < n4; i += gridDim.x * blockDim.x)
        reinterpret_cast<float4*>(p)[i] = z;
}

// split f32 -> (hi, lo) bf16 pair, 4 elements/thread
__global__ void split_kernel(const float* __restrict__ x,
                             __nv_bfloat16* __restrict__ hi,
                             __nv_bfloat16* __restrict__ lo, int n4) {
    for (int i = blockIdx.x * blockDim.x + threadIdx.x; i < n4; i += gridDim.x * blockDim.x) {
        float4 v = reinterpret_cast<const float4*>(x)[i];
        float a[4] = {v.x, v.y, v.z, v.w};
        __nv_bfloat16 h[4], l[4];
        #pragma unroll
        for (int q = 0; q < 4; q++) {
            h[q] = __float2bfloat16(a[q]);
            l[q] = __float2bfloat16(a[q] - __bfloat162float(h[q]));
        }
        reinterpret_cast<uint2*>(hi)[i] =
            make_uint2(*(uint32_t*)&h[0] | (*(uint32_t*)&h[1] << 16) * 0 +
                       ((uint32_t)*(uint16_t*)&h[1] << 16) | (uint32_t)*(uint16_t*)&h[0],
                       ((uint32_t)*(uint16_t*)&h[3] << 16) | (uint32_t)*(uint16_t*)&h[2]);
        reinterpret_cast<uint2*>(lo)[i] =
            make_uint2(((uint32_t)*(uint16_t*)&l[1] << 16) | (uint32_t)*(uint16_t*)&l[0],
                       ((uint32_t)*(uint16_t*)&l[3] << 16) | (uint32_t)*(uint16_t*)&l[2]);
    }
}

// SpMM scatter with vector atomics: agg[dst] += w*inv[src]*x[src]
__global__ void spmm_kernel(const float* __restrict__ x,
                            const float* __restrict__ inv,
                            const int* __restrict__ ei,
                            const float* __restrict__ ew,
                            float* __restrict__ agg) {
    int e = blockIdx.x * 2 + (threadIdx.x >> 7);
    int t = threadIdx.x & 127;
    int dst = ei[e];
    int src = ei[E_EDGES + e];
    float s = ew[e] * inv[src];
    float4 v = reinterpret_cast<const float4*>(x)[src * (D_DIM / 4) + t];
    redg_v4(agg + (size_t)dst * D_DIM + t * 4, s * v.x, s * v.y, s * v.z, s * v.w);
}

// L2 normalize rows of x and emit split-bf16 (hi + lo ~= x_normalized)
__global__ void l2norm_split_kernel(const float* __restrict__ x,
                                    __nv_bfloat16* __restrict__ hi,
                                    __nv_bfloat16* __restrict__ lo) {
    int row = blockIdx.x;
    const float4 v = reinterpret_cast<const float4*>(x)[row * (D_DIM / 4) + threadIdx.x];
    float s = v.x * v.x + v.y * v.y + v.z * v.z + v.w * v.w;
    #pragma unroll
    for (int o = 16; o > 0; o >>= 1) s += __shfl_down_sync(0xffffffffu, s, o);
    __shared__ float red[4];
    __shared__ float sscale;
    if ((threadIdx.x & 31) == 0) red[threadIdx.x >> 5] = s;
    __syncthreads();
    if (threadIdx.x == 0) {
        float t = red[0] + red[1] + red[2] + red[3];
        sscale = 1.0f / fmaxf(sqrtf(t), 1e-12f);
    }
    __syncthreads();
    float sc = sscale;
    float a[4] = {v.x * sc, v.y * sc, v.z * sc, v.w * sc};
    int base = row * D_DIM + threadIdx.x * 4;
    #pragma unroll
    for (int i = 0; i < 4; i++) {
        __nv_bfloat16 h = __float2bfloat16(a[i]);
        hi[base + i] = h;
        lo[base + i] = __float2bfloat16(a[i] - __bfloat162float(h));
    }
}

// ==================== shared mma tile machinery ============================
#define SIM_BM 128
#define SIM_KC 32
#define ROWB   80                       // padded row stride (bytes)
#define OPSZ   (SIM_BM * ROWB)          // 10240 B per operand tile
#define STG    (4 * OPSZ)               // Ahi,Alo,Bhi,Blo per stage: 40960 B
#define SIM_SMEM (2 * STG)              // 81920 B
#define NCHUNK (D_DIM / SIM_KC)         // 16

// Main loop shared by sim and linear kernels: accumulates 3-term split-bf16
// 128x128 NT product of gA x gB^T into acc[4][4][4] (warp layout 2x4, 64x32).
struct MmaCtx {
    float acc[4][4][4];
};

__device__ __forceinline__ void mma_mainloop(
    const __nv_bfloat16* gA0, const __nv_bfloat16* gA1,
    const __nv_bfloat16* gB0, const __nv_bfloat16* gB1,
    uint32_t sb, int tid, int wm, int wn, int lane, MmaCtx& cx) {

    #pragma unroll
    for (int i = 0; i < 4; i++)
        #pragma unroll
        for (int j = 0; j < 4; j++)
            #pragma unroll
            for (int q = 0; q < 4; q++) cx.acc[i][j][q] = 0.f;

    const __nv_bfloat16* gA[2] = {gA0, gA1};
    const __nv_bfloat16* gB[2] = {gB0, gB1};

    auto load_chunk = [&](int c) {
        uint32_t st = sb + (uint32_t)(c & 1) * STG;
        int koff = c * SIM_KC;
        #pragma unroll
        for (int h = 0; h < 2; h++) {
            #pragma unroll
            for (int i = 0; i < 2; i++) {
                int idx = i * 256 + tid;
                int r = idx >> 2, cc = idx & 3;
                CPA16(st + h * OPSZ + r * ROWB + cc * 16,
                      gA[h] + (size_t)r * D_DIM + koff + cc * 8);
                CPA16(st + (2 + h) * OPSZ + r * ROWB + cc * 16,
                      gB[h] + (size_t)r * D_DIM + koff + cc * 8);
            }
        }
        CPA_COMMIT();
    };

    load_chunk(0);
    load_chunk(1);

    for (int c = 0; c < NCHUNK; c++) {
        if (c < NCHUNK - 1) asm volatile("cp.async.wait_group 1;" ::: "memory");
        else                asm volatile("cp.async.wait_group 0;" ::: "memory");
        __syncthreads();

        uint32_t st = sb + (uint32_t)(c & 1) * STG;
        #pragma unroll
        for (int ks = 0; ks < 2; ks++) {
            uint32_t afr[2][4][4];
            {
                int rowA = wm * 64 + (lane & 15);
                int chk = 2 * ks + (lane >> 4);
                uint32_t off = (uint32_t)(rowA * ROWB + chk * 16);
                #pragma unroll
                for (int h = 0; h < 2; h++)
                    #pragma unroll
                    for (int mi = 0; mi < 4; mi++)
                        ldm_x4(afr[h][mi], st + h * OPSZ + off + (uint32_t)(mi * 16 * ROWB));
            }
            uint32_t bfr[2][4][2];
            {
                int rowB = wn * 32 + ((lane >> 4) & 1) * 8 + (lane & 7);
                int chk = 2 * ks + ((lane >> 3) & 1);
                uint32_t off = (uint32_t)(rowB * ROWB + chk * 16);
                #pragma unroll
                for (int h = 0; h < 2; h++)
                    #pragma unroll
                    for (int jp = 0; jp < 2; jp++) {
                        uint32_t r4[4];
                        ldm_x4(r4, st + (2 + h) * OPSZ + off + (uint32_t)(jp * 16 * ROWB));
                        bfr[h][jp * 2 + 0][0] = r4[0]; bfr[h][jp * 2 + 0][1] = r4[1];
                        bfr[h][jp * 2 + 1][0] = r4[2]; bfr[h][jp * 2 + 1][1] = r4[3];
                    }
            }
            #pragma unroll
            for (int mi = 0; mi < 4; mi++)
                #pragma unroll
                for (int nj = 0; nj < 4; nj++) {
                    mma_bf16(cx.acc[mi][nj], afr[0][mi], bfr[0][nj]);  // hi*hi
                    mma_bf16(cx.acc[mi][nj], afr[0][mi], bfr[1][nj]);  // hi*lo
                    mma_bf16(cx.acc[mi][nj], afr[1][mi], bfr[0][nj]);  // lo*hi
                }
        }
        __syncthreads();
        if (c + 2 < NCHUNK) load_chunk(c + 2);
    }
}

// ==================== linear layer: elu(X @ W^T + b) =======================
__global__ __launch_bounds__(256)
void lin_mma_kernel(const __nv_bfloat16* __restrict__ Xhi,
                    const __nv_bfloat16* __restrict__ Xlo,
                    const __nv_bfloat16* __restrict__ Whi,
                    const __nv_bfloat16* __restrict__ Wlo,
                    const float* __restrict__ bias,
                    float* __restrict__ Cout) {
    extern __shared__ char smem[];
    const uint32_t sb = smem_u32(smem);
    const int tid = threadIdx.x;
    const int wid = tid >> 5, lane = tid & 31;
    const int wm = wid >> 2, wn = wid & 3;
    const int row0 = blockIdx.y * SIM_BM, col0 = blockIdx.x * SIM_BM;

    MmaCtx cx;
    mma_mainloop(Xhi + (size_t)row0 * D_DIM, Xlo + (size_t)row0 * D_DIM,
                 Whi + (size_t)col0 * D_DIM, Wlo + (size_t)col0 * D_DIM,
                 sb, tid, wm, wn, lane, cx);

    // epilogue: bias + elu, direct float2 stores
    #pragma unroll
    for (int mi = 0; mi < 4; mi++) {
        int r = row0 + wm * 64 + mi * 16 + (lane >> 2);
        #pragma unroll
        for (int nj = 0; nj < 4; nj++) {
            int c = col0 + wn * 32 + nj * 8 + (lane & 3) * 2;
            float b0 = bias[c], b1 = bias[c + 1];
            float z0 = cx.acc[mi][nj][0] + b0, z1 = cx.acc[mi][nj][1] + b1;
            float z2 = cx.acc[mi][nj][2] + b0, z3 = cx.acc[mi][nj][3] + b1;
            z0 = (z0 > 0.f) ? z0 : expm1f(z0);
            z1 = (z1 > 0.f) ? z1 : expm1f(z1);
            z2 = (z2 > 0.f) ? z2 : expm1f(z2);
            z3 = (z3 > 0.f) ? z3 : expm1f(z3);
            *reinterpret_cast<float2*>(Cout + (size_t)r * D_DIM + c) = make_float2(z0, z1);
            *reinterpret_cast<float2*>(Cout + (size_t)(r + 8) * D_DIM + c) = make_float2(z2, z3);
        }
    }
}

// ==================== similarity: relu(emb @ emb^T), symmetric =============
__global__ __launch_bounds__(256)
void sim_mma_kernel(const __nv_bfloat16* __restrict__ hi,
                    const __nv_bfloat16* __restrict__ lo,
                    float* __restrict__ out) {
    extern __shared__ char smem[];
    const uint32_t sb = smem_u32(smem);
    const int tid = threadIdx.x;
    const int wid = tid >> 5, lane = tid & 31;
    const int wm = wid >> 2, wn = wid & 3;

    int k = blockIdx.x;
    int bi = (int)((sqrtf(8.f * (float)k + 1.f) - 1.f) * 0.5f);
    while ((bi + 1) * (bi + 2) / 2 <= k) bi++;
    while (bi * (bi + 1) / 2 > k) bi--;
    int bj = k - bi * (bi + 1) / 2;
    const int row0 = bi * SIM_BM, col0 = bj * SIM_BM;

    MmaCtx cx;
    mma_mainloop(hi + (size_t)row0 * D_DIM, lo + (size_t)row0 * D_DIM,
                 hi + (size_t)col0 * D_DIM, lo + (size_t)col0 * D_DIM,
                 sb, tid, wm, wn, lane, cx);

    __syncthreads();
    float* Csm = reinterpret_cast<float*>(smem);   // 128 x 129 floats
    #pragma unroll
    for (int mi = 0; mi < 4; mi++) {
        int r = wm * 64 + mi * 16 + (lane >> 2);
        #pragma unroll
        for (int nj = 0; nj < 4; nj++) {
            int cc = wn * 32 + nj * 8 + (lane & 3) * 2;
            Csm[r * 129 + cc]           = cx.acc[mi][nj][0];
            Csm[r * 129 + cc + 1]       = cx.acc[mi][nj][1];
            Csm[(r + 8) * 129 + cc]     = cx.acc[mi][nj][2];
            Csm[(r + 8) * 129 + cc + 1] = cx.acc[mi][nj][3];
        }
    }
    __syncthreads();

    #pragma unroll 4
    for (int i = 0; i < 64; i++) {
        int idx = i * 256 + tid;
        int r = idx >> 7, cc = idx & 127;
        float v = Csm[r * 129 + cc];
        v = (v > 0.f) ? v : 0.f;
        out[(size_t)(row0 + r) * N_NODES + col0 + cc] = v;
    }
    if (bi != bj) {
        #pragma unroll 4
        for (int i = 0; i < 64; i++) {
            int idx = i * 256 + tid;
            int rr = idx & 127, cc = idx >> 7;
            float v = Csm[rr * 129 + cc];
            v = (v > 0.f) ? v : 0.f;
            out[(size_t)(col0 + cc) * N_NODES + row0 + rr] = v;
        }
    }
}

// ===========================================================================
extern "C" void kernel_launch(void* const* d_in, const int* in_sizes, int n_in,
                              void* d_out, int out_size) {
    const float* x  = (const float*)d_in[0];
    const int*   ei = (const int*)d_in[1];
    const float* ew = (const float*)d_in[2];
    const float* W  = (const float*)d_in[3];
    const float* b  = (const float*)d_in[4];
    float* out = (float*)d_out;

    float *A, *B, *C, *inv;
    __nv_bfloat16 *hi, *lo, *Whi, *Wlo;
    cudaGetSymbolAddress((void**)&A, g_bufA);
    cudaGetSymbolAddress((void**)&B, g_bufB);
    cudaGetSymbolAddress((void**)&C, g_bufC);
    cudaGetSymbolAddress((void**)&inv, g_inv);
    cudaGetSymbolAddress((void**)&hi, g_hi);
    cudaGetSymbolAddress((void**)&lo, g_lo);
    cudaGetSymbolAddress((void**)&Whi, g_Whi);
    cudaGetSymbolAddress((void**)&Wlo, g_Wlo);

    cudaFuncSetAttribute(sim_mma_kernel,
                         cudaFuncAttributeMaxDynamicSharedMemorySize, SIM_SMEM);
    cudaFuncSetAttribute(lin_mma_kernel,
                         cudaFuncAttributeMaxDynamicSharedMemorySize, SIM_SMEM);

    dim3 gLin(D_DIM / SIM_BM, N_NODES / SIM_BM);   // 4 x 64

    // W -> hi/lo (once per launch)
    split_kernel<<<128, 256>>>(W, Whi, Wlo, D_DIM * D_DIM / 4);

    // ---- layer 1 ----
    rowsum_inv_kernel<<<N_NODES, 128>>>(x, inv);
    zero_kernel<<<2048, 256>>>(B, N_NODES * D_DIM / 4);
    spmm_kernel<<<E_EDGES / 2, 256>>>(x, inv, ei, ew, B);
    split_kernel<<<2048, 256>>>(B, hi, lo, N_NODES * D_DIM / 4);
    lin_mma_kernel<<<gLin, 256, SIM_SMEM>>>(hi, lo, Whi, Wlo, b, C);

    // ---- layer 2 ----
    rowsum_inv_kernel<<<N_NODES, 128>>>(C, inv);
    zero_kernel<<<2048, 256>>>(B, N_NODES * D_DIM / 4);
    spmm_kernel<<<E_EDGES / 2, 256>>>(C, inv, ei, ew, B);
    split_kernel<<<2048, 256>>>(B, hi, lo, N_NODES * D_DIM / 4);
    lin_mma_kernel<<<gLin, 256, SIM_SMEM>>>(hi, lo, Whi, Wlo, b, A);

    // ---- normalize + split to bf16 hi/lo ----
    l2norm_split_kernel<<<N_NODES, 128>>>(A, hi, lo);

    // ---- similarity: symmetric tiles, mma.sync split-bf16 + relu ----
    int nblk = (N_NODES / SIM_BM);             // 64
    int ntri = nblk * (nblk + 1) / 2;          // 2080
    sim_mma_kernel<<<ntri, 256, SIM_SMEM>>>(hi, lo, out);
}

// round 5
// speedup vs baseline: 4.0730x; 1.2123x over previous
#include <cuda_runtime.h>
#include <cuda_bf16.h>
#include <math.h>
#include <stdint.h>

#define N_NODES 8192
#define D_DIM   512
#define E_EDGES 262144

// Scratch (allocation-free rule: device globals)
__device__ float g_bufA[N_NODES * D_DIM];  // layer-2 output / emb (f32)
__device__ float g_bufC[N_NODES * D_DIM];  // layer-1 output
__device__ float g_inv[N_NODES];           // 1/(rowsum+1e-4)
__device__ float g_rowsum[N_NODES];        // fused rowsum accumulator
__device__ __nv_bfloat16 g_hi[N_NODES * D_DIM];
__device__ __nv_bfloat16 g_lo[N_NODES * D_DIM];
__device__ __nv_bfloat16 g_Whi[D_DIM * D_DIM];
__device__ __nv_bfloat16 g_Wlo[D_DIM * D_DIM];
// CSR scratch
__device__ int   g_cnt[N_NODES];
__device__ int   g_off[N_NODES + 1];
__device__ int   g_cur[N_NODES];
__device__ int   g_csr_src[E_EDGES];
__device__ float g_csr_w[E_EDGES];

// ============================ PTX helpers (base PTX only!) =================
__device__ __forceinline__ uint32_t smem_u32(const void* p) {
    uint32_t a;
    asm("{ .reg .u64 t; cvta.to.shared.u64 t, %1; cvt.u32.u64 %0, t; }"
        : "=r"(a) : "l"(p));
    return a;
}
#define CPA16(s, g) \
    asm volatile("cp.async.cg.shared.global [%0], [%1], 16;" :: "r"(s), "l"(g))
#define CPA_COMMIT() asm volatile("cp.async.commit_group;" ::: "memory")

__device__ __forceinline__ void ldm_x4(uint32_t* r, uint32_t addr) {
    asm volatile("ldmatrix.sync.aligned.m8n8.x4.shared.b16 {%0,%1,%2,%3}, [%4];"
                 : "=r"(r[0]), "=r"(r[1]), "=r"(r[2]), "=r"(r[3]) : "r"(addr));
}
__device__ __forceinline__ void mma_bf16(float* c, const uint32_t* a,
                                         const uint32_t* b) {
    asm volatile(
        "mma.sync.aligned.m16n8k16.row.col.f32.bf16.bf16.f32 "
        "{%0,%1,%2,%3}, {%4,%5,%6,%7}, {%8,%9}, {%0,%1,%2,%3};"
        : "+f"(c[0]), "+f"(c[1]), "+f"(c[2]), "+f"(c[3])
        : "r"(a[0]), "r"(a[1]), "r"(a[2]), "r"(a[3]), "r"(b[0]), "r"(b[1]));
}

// ============================ small kernels ================================
__global__ void rowsum_inv_kernel(const float* __restrict__ x,
                                  float* __restrict__ inv) {
    int row = blockIdx.x;
    const float4 v = reinterpret_cast<const float4*>(x)[row * (D_DIM / 4) + threadIdx.x];
    float s = v.x + v.y + v.z + v.w;
    #pragma unroll
    for (int o = 16; o > 0; o >>= 1) s += __shfl_down_sync(0xffffffffu, s, o);
    __shared__ float red[4];
    if ((threadIdx.x & 31) == 0) red[threadIdx.x >> 5] = s;
    __syncthreads();
    if (threadIdx.x == 0) {
        float t = red[0] + red[1] + red[2] + red[3];
        inv[row] = 1.0f / (t + 1e-4f);
    }
}

__global__ void zero_i32_kernel(int* __restrict__ p, int n) {
    int i = blockIdx.x * blockDim.x + threadIdx.x;
    if (i < n) p[i] = 0;
}
__global__ void zero_f32_kernel(float* __restrict__ p, int n) {
    int i = blockIdx.x * blockDim.x + threadIdx.x;
    if (i < n) p[i] = 0.f;
}
__global__ void inv_from_sum_kernel(const float* __restrict__ sum,
                                    float* __restrict__ inv, int n) {
    int i = blockIdx.x * blockDim.x + threadIdx.x;
    if (i < n) inv[i] = 1.0f / (sum[i] + 1e-4f);
}

// split f32 -> (hi, lo) bf16 pair, 4 elements/thread (for W)
__global__ void split_kernel(const float* __restrict__ x,
                             __nv_bfloat16* __restrict__ hi,
                             __nv_bfloat16* __restrict__ lo, int n4) {
    for (int i = blockIdx.x * blockDim.x + threadIdx.x; i < n4; i += gridDim.x * blockDim.x) {
        float4 v = reinterpret_cast<const float4*>(x)[i];
        float a[4] = {v.x, v.y, v.z, v.w};
        uint16_t h[4], l[4];
        #pragma unroll
        for (int q = 0; q < 4; q++) {
            __nv_bfloat16 hb = __float2bfloat16(a[q]);
            __nv_bfloat16 lb = __float2bfloat16(a[q] - __bfloat162float(hb));
            h[q] = *reinterpret_cast<uint16_t*>(&hb);
            l[q] = *reinterpret_cast<uint16_t*>(&lb);
        }
        reinterpret_cast<uint2*>(hi)[i] =
            make_uint2(((uint32_t)h[1] << 16) | h[0], ((uint32_t)h[3] << 16) | h[2]);
        reinterpret_cast<uint2*>(lo)[i] =
            make_uint2(((uint32_t)l[1] << 16) | l[0], ((uint32_t)l[3] << 16) | l[2]);
    }
}

// ============================ CSR build ====================================
__global__ void hist_kernel(const int* __restrict__ ei, int* __restrict__ cnt) {
    int e = blockIdx.x * blockDim.x + threadIdx.x;
    if (e < E_EDGES) atomicAdd(&cnt[ei[e]], 1);
}

__global__ void scan_kernel(const int* __restrict__ cnt,
                            int* __restrict__ off, int* __restrict__ cur) {
    __shared__ int part[1024];
    int t = threadIdx.x;
    int local[8], s = 0;
    #pragma unroll
    for (int i = 0; i < 8; i++) { local[i] = cnt[t * 8 + i]; s += local[i]; }
    part[t] = s;
    __syncthreads();
    for (int d = 1; d < 1024; d <<= 1) {
        int v = (t >= d) ? part[t - d] : 0;
        __syncthreads();
        part[t] += v;
        __syncthreads();
    }
    int base = (t > 0) ? part[t - 1] : 0;
    #pragma unroll
    for (int i = 0; i < 8; i++) {
        off[t * 8 + i] = base;
        cur[t * 8 + i] = base;
        base += local[i];
    }
    if (t == 0) off[N_NODES] = E_EDGES;
}

__global__ void fill_kernel(const int* __restrict__ ei, const float* __restrict__ ew,
                            int* __restrict__ cur,
                            int* __restrict__ csr_src, float* __restrict__ csr_w) {
    int e = blockIdx.x * blockDim.x + threadIdx.x;
    if (e >= E_EDGES) return;
    int dst = ei[e];
    int pos = atomicAdd(&cur[dst], 1);
    csr_src[pos] = ei[E_EDGES + e];
    csr_w[pos] = ew[e];
}

// ============ CSR SpMM + fused split: hi/lo = split(sum w*inv*x[src]) ======
// one 128-thread block per dst row; thread owns one float4 of the feature dim
__global__ __launch_bounds__(128)
void spmm_csr_kernel(const float* __restrict__ x, const float* __restrict__ inv,
                     const int* __restrict__ off,
                     const int* __restrict__ csr_src, const float* __restrict__ csr_w,
                     __nv_bfloat16* __restrict__ hi, __nv_bfloat16* __restrict__ lo) {
    int row = blockIdx.x;
    int t = threadIdx.x;
    int s = off[row], e = off[row + 1];
    float4 acc = make_float4(0.f, 0.f, 0.f, 0.f);
    for (int j = s; j < e; j++) {
        int src = __ldg(csr_src + j);
        float w = __ldg(csr_w + j) * __ldg(inv + src);
        float4 v = __ldg(reinterpret_cast<const float4*>(x) + src * (D_DIM / 4) + t);
        acc.x = fmaf(w, v.x, acc.x);
        acc.y = fmaf(w, v.y, acc.y);
        acc.z = fmaf(w, v.z, acc.z);
        acc.w = fmaf(w, v.w, acc.w);
    }
    float a[4] = {acc.x, acc.y, acc.z, acc.w};
    uint16_t h[4], l[4];
    #pragma unroll
    for (int q = 0; q < 4; q++) {
        __nv_bfloat16 hb = __float2bfloat16(a[q]);
        __nv_bfloat16 lb = __float2bfloat16(a[q] - __bfloat162float(hb));
        h[q] = *reinterpret_cast<uint16_t*>(&hb);
        l[q] = *reinterpret_cast<uint16_t*>(&lb);
    }
    int i = row * (D_DIM / 4) + t;
    reinterpret_cast<uint2*>(hi)[i] =
        make_uint2(((uint32_t)h[1] << 16) | h[0], ((uint32_t)h[3] << 16) | h[2]);
    reinterpret_cast<uint2*>(lo)[i] =
        make_uint2(((uint32_t)l[1] << 16) | l[0], ((uint32_t)l[3] << 16) | l[2]);
}

// L2 normalize rows of x and emit split-bf16 (hi + lo ~= x_normalized)
__global__ void l2norm_split_kernel(const float* __restrict__ x,
                                    __nv_bfloat16* __restrict__ hi,
                                    __nv_bfloat16* __restrict__ lo) {
    int row = blockIdx.x;
    const float4 v = reinterpret_cast<const float4*>(x)[row * (D_DIM / 4) + threadIdx.x];
    float s = v.x * v.x + v.y * v.y + v.z * v.z + v.w * v.w;
    #pragma unroll
    for (int o = 16; o > 0; o >>= 1) s += __shfl_down_sync(0xffffffffu, s, o);
    __shared__ float red[4];
    __shared__ float sscale;
    if ((threadIdx.x & 31) == 0) red[threadIdx.x >> 5] = s;
    __syncthreads();
    if (threadIdx.x == 0) {
        float t = red[0] + red[1] + red[2] + red[3];
        sscale = 1.0f / fmaxf(sqrtf(t), 1e-12f);
    }
    __syncthreads();
    float sc = sscale;
    float a[4] = {v.x * sc, v.y * sc, v.z * sc, v.w * sc};
    int base = row * D_DIM + threadIdx.x * 4;
    #pragma unroll
    for (int i = 0; i < 4; i++) {
        __nv_bfloat16 h = __float2bfloat16(a[i]);
        hi[base + i] = h;
        lo[base + i] = __float2bfloat16(a[i] - __bfloat162float(h));
    }
}

// ==================== shared mma tile machinery ============================
#define SIM_BM 128
#define SIM_KC 32
#define ROWB   80
#define OPSZ   (SIM_BM * ROWB)
#define STG    (4 * OPSZ)
#define SIM_SMEM (2 * STG)
#define NCHUNK (D_DIM / SIM_KC)

struct MmaCtx { float acc[4][4][4]; };

__device__ __forceinline__ void mma_mainloop(
    const __nv_bfloat16* gA0, const __nv_bfloat16* gA1,
    const __nv_bfloat16* gB0, const __nv_bfloat16* gB1,
    uint32_t sb, int tid, int wm, int wn, int lane, MmaCtx& cx) {

    #pragma unroll
    for (int i = 0; i < 4; i++)
        #pragma unroll
        for (int j = 0; j < 4; j++)
            #pragma unroll
            for (int q = 0; q < 4; q++) cx.acc[i][j][q] = 0.f;

    const __nv_bfloat16* gA[2] = {gA0, gA1};
    const __nv_bfloat16* gB[2] = {gB0, gB1};

    auto load_chunk = [&](int c) {
        uint32_t st = sb + (uint32_t)(c & 1) * STG;
        int koff = c * SIM_KC;
        #pragma unroll
        for (int h = 0; h < 2; h++) {
            #pragma unroll
            for (int i = 0; i < 2; i++) {
                int idx = i * 256 + tid;
                int r = idx >> 2, cc = idx & 3;
                CPA16(st + h * OPSZ + r * ROWB + cc * 16,
                      gA[h] + (size_t)r * D_DIM + koff + cc * 8);
                CPA16(st + (2 + h) * OPSZ + r * ROWB + cc * 16,
                      gB[h] + (size_t)r * D_DIM + koff + cc * 8);
            }
        }
        CPA_COMMIT();
    };

    load_chunk(0);
    load_chunk(1);

    for (int c = 0; c < NCHUNK; c++) {
        if (c < NCHUNK - 1) asm volatile("cp.async.wait_group 1;" ::: "memory");
        else                asm volatile("cp.async.wait_group 0;" ::: "memory");
        __syncthreads();

        uint32_t st = sb + (uint32_t)(c & 1) * STG;
        #pragma unroll
        for (int ks = 0; ks < 2; ks++) {
            uint32_t afr[2][4][4];
            {
                int rowA = wm * 64 + (lane & 15);
                int chk = 2 * ks + (lane >> 4);
                uint32_t off = (uint32_t)(rowA * ROWB + chk * 16);
                #pragma unroll
                for (int h = 0; h < 2; h++)
                    #pragma unroll
                    for (int mi = 0; mi < 4; mi++)
                        ldm_x4(afr[h][mi], st + h * OPSZ + off + (uint32_t)(mi * 16 * ROWB));
            }
            uint32_t bfr[2][4][2];
            {
                int rowB = wn * 32 + ((lane >> 4) & 1) * 8 + (lane & 7);
                int chk = 2 * ks + ((lane >> 3) & 1);
                uint32_t off = (uint32_t)(rowB * ROWB + chk * 16);
                #pragma unroll
                for (int h = 0; h < 2; h++)
                    #pragma unroll
                    for (int jp = 0; jp < 2; jp++) {
                        uint32_t r4[4];
                        ldm_x4(r4, st + (2 + h) * OPSZ + off + (uint32_t)(jp * 16 * ROWB));
                        bfr[h][jp * 2 + 0][0] = r4[0]; bfr[h][jp * 2 + 0][1] = r4[1];
                        bfr[h][jp * 2 + 1][0] = r4[2]; bfr[h][jp * 2 + 1][1] = r4[3];
                    }
            }
            #pragma unroll
            for (int mi = 0; mi < 4; mi++)
                #pragma unroll
                for (int nj = 0; nj < 4; nj++) {
                    mma_bf16(cx.acc[mi][nj], afr[0][mi], bfr[0][nj]);
                    mma_bf16(cx.acc[mi][nj], afr[0][mi], bfr[1][nj]);
                    mma_bf16(cx.acc[mi][nj], afr[1][mi], bfr[0][nj]);
                }
        }
        __syncthreads();
        if (c + 2 < NCHUNK) load_chunk(c + 2);
    }
}

// ==================== linear layer: elu(X @ W^T + b) [+ rowsum] ============
__global__ __launch_bounds__(256)
void lin_mma_kernel(const __nv_bfloat16* __restrict__ Xhi,
                    const __nv_bfloat16* __restrict__ Xlo,
                    const __nv_bfloat16* __restrict__ Whi,
                    const __nv_bfloat16* __restrict__ Wlo,
                    const float* __restrict__ bias,
                    float* __restrict__ Cout,
                    float* __restrict__ rowsum) {
    extern __shared__ char smem[];
    const uint32_t sb = smem_u32(smem);
    const int tid = threadIdx.x;
    const int wid = tid >> 5, lane = tid & 31;
    const int wm = wid >> 2, wn = wid & 3;
    const int row0 = blockIdx.y * SIM_BM, col0 = blockIdx.x * SIM_BM;

    MmaCtx cx;
    mma_mainloop(Xhi + (size_t)row0 * D_DIM, Xlo + (size_t)row0 * D_DIM,
                 Whi + (size_t)col0 * D_DIM, Wlo + (size_t)col0 * D_DIM,
                 sb, tid, wm, wn, lane, cx);

    #pragma unroll
    for (int mi = 0; mi < 4; mi++) {
        int r = row0 + wm * 64 + mi * 16 + (lane >> 2);
        float rs0 = 0.f, rs1 = 0.f;   // partial row sums for r, r+8
        #pragma unroll
        for (int nj = 0; nj < 4; nj++) {
            int c = col0 + wn * 32 + nj * 8 + (lane & 3) * 2;
            float b0 = bias[c], b1 = bias[c + 1];
            float z0 = cx.acc[mi][nj][0] + b0, z1 = cx.acc[mi][nj][1] + b1;
            float z2 = cx.acc[mi][nj][2] + b0, z3 = cx.acc[mi][nj][3] + b1;
            z0 = (z0 > 0.f) ? z0 : expm1f(z0);
            z1 = (z1 > 0.f) ? z1 : expm1f(z1);
            z2 = (z2 > 0.f) ? z2 : expm1f(z2);
            z3 = (z3 > 0.f) ? z3 : expm1f(z3);
            rs0 += z0 + z1;
            rs1 += z2 + z3;
            *reinterpret_cast<float2*>(Cout + (size_t)r * D_DIM + c) = make_float2(z0, z1);
            *reinterpret_cast<float2*>(Cout + (size_t)(r + 8) * D_DIM + c) = make_float2(z2, z3);
        }
        if (rowsum) {
            rs0 += __shfl_xor_sync(0xffffffffu, rs0, 1);
            rs0 += __shfl_xor_sync(0xffffffffu, rs0, 2);
            rs1 += __shfl_xor_sync(0xffffffffu, rs1, 1);
            rs1 += __shfl_xor_sync(0xffffffffu, rs1, 2);
            if ((lane & 3) == 0) {
                atomicAdd(rowsum + r, rs0);
                atomicAdd(rowsum + r + 8, rs1);
            }
        }
    }
}

// ==================== similarity: relu(emb @ emb^T), symmetric =============
__global__ __launch_bounds__(256)
void sim_mma_kernel(const __nv_bfloat16* __restrict__ hi,
                    const __nv_bfloat16* __restrict__ lo,
                    float* __restrict__ out) {
    extern __shared__ char smem[];
    const uint32_t sb = smem_u32(smem);
    const int tid = threadIdx.x;
    const int wid = tid >> 5, lane = tid & 31;
    const int wm = wid >> 2, wn = wid & 3;

    int k = blockIdx.x;
    int bi = (int)((sqrtf(8.f * (float)k + 1.f) - 1.f) * 0.5f);
    while ((bi + 1) * (bi + 2) / 2 <= k) bi++;
    while (bi * (bi + 1) / 2 > k) bi--;
    int bj = k - bi * (bi + 1) / 2;
    const int row0 = bi * SIM_BM, col0 = bj * SIM_BM;

    MmaCtx cx;
    mma_mainloop(hi + (size_t)row0 * D_DIM, lo + (size_t)row0 * D_DIM,
                 hi + (size_t)col0 * D_DIM, lo + (size_t)col0 * D_DIM,
                 sb, tid, wm, wn, lane, cx);

    __syncthreads();
    float* Csm = reinterpret_cast<float*>(smem);   // 128 x 129 floats
    #pragma unroll
    for (int mi = 0; mi < 4; mi++) {
        int r = wm * 64 + mi * 16 + (lane >> 2);
        #pragma unroll
        for (int nj = 0; nj < 4; nj++) {
            int cc = wn * 32 + nj * 8 + (lane & 3) * 2;
            Csm[r * 129 + cc]           = cx.acc[mi][nj][0];
            Csm[r * 129 + cc + 1]       = cx.acc[mi][nj][1];
            Csm[(r + 8) * 129 + cc]     = cx.acc[mi][nj][2];
            Csm[(r + 8) * 129 + cc + 1] = cx.acc[mi][nj][3];
        }
    }
    __syncthreads();

    #pragma unroll 4
    for (int i = 0; i < 64; i++) {
        int idx = i * 256 + tid;
        int r = idx >> 7, cc = idx & 127;
        float v = Csm[r * 129 + cc];
        v = (v > 0.f) ? v : 0.f;
        out[(size_t)(row0 + r) * N_NODES + col0 + cc] = v;
    }
    if (bi != bj) {
        #pragma unroll 4
        for (int i = 0; i < 64; i++) {
            int idx = i * 256 + tid;
            int rr = idx & 127, cc = idx >> 7;
            float v = Csm[rr * 129 + cc];
            v = (v > 0.f) ? v : 0.f;
            out[(size_t)(col0 + cc) * N_NODES + row0 + rr] = v;
        }
    }
}

// ===========================================================================
extern "C" void kernel_launch(void* const* d_in, const int* in_sizes, int n_in,
                              void* d_out, int out_size) {
    const float* x  = (const float*)d_in[0];
    const int*   ei = (const int*)d_in[1];
    const float* ew = (const float*)d_in[2];
    const float* W  = (const float*)d_in[3];
    const float* b  = (const float*)d_in[4];
    float* out = (float*)d_out;

    float *A, *C, *inv, *rowsum, *csr_w;
    __nv_bfloat16 *hi, *lo, *Whi, *Wlo;
    int *cnt, *off, *cur, *csr_src;
    cudaGetSymbolAddress((void**)&A, g_bufA);
    cudaGetSymbolAddress((void**)&C, g_bufC);
    cudaGetSymbolAddress((void**)&inv, g_inv);
    cudaGetSymbolAddress((void**)&rowsum, g_rowsum);
    cudaGetSymbolAddress((void**)&hi, g_hi);
    cudaGetSymbolAddress((void**)&lo, g_lo);
    cudaGetSymbolAddress((void**)&Whi, g_Whi);
    cudaGetSymbolAddress((void**)&Wlo, g_Wlo);
    cudaGetSymbolAddress((void**)&cnt, g_cnt);
    cudaGetSymbolAddress((void**)&off, g_off);
    cudaGetSymbolAddress((void**)&cur, g_cur);
    cudaGetSymbolAddress((void**)&csr_src, g_csr_src);
    cudaGetSymbolAddress((void**)&csr_w, g_csr_w);

    cudaFuncSetAttribute(sim_mma_kernel,
                         cudaFuncAttributeMaxDynamicSharedMemorySize, SIM_SMEM);
    cudaFuncSetAttribute(lin_mma_kernel,
                         cudaFuncAttributeMaxDynamicSharedMemorySize, SIM_SMEM);

    dim3 gLin(D_DIM / SIM_BM, N_NODES / SIM_BM);   // 4 x 64

    // ---- one-time per launch: W split + CSR build ----
    split_kernel<<<128, 256>>>(W, Whi, Wlo, D_DIM * D_DIM / 4);
    zero_i32_kernel<<<N_NODES / 256, 256>>>(cnt, N_NODES);
    hist_kernel<<<E_EDGES / 512, 512>>>(ei, cnt);
    scan_kernel<<<1, 1024>>>(cnt, off, cur);
    fill_kernel<<<E_EDGES / 512, 512>>>(ei, ew, cur, csr_src, csr_w);

    // ---- layer 1 ----
    rowsum_inv_kernel<<<N_NODES, 128>>>(x, inv);
    zero_f32_kernel<<<N_NODES / 256, 256>>>(rowsum, N_NODES);
    spmm_csr_kernel<<<N_NODES, 128>>>(x, inv, off, csr_src, csr_w, hi, lo);
    lin_mma_kernel<<<gLin, 256, SIM_SMEM>>>(hi, lo, Whi, Wlo, b, C, rowsum);

    // ---- layer 2 ----
    inv_from_sum_kernel<<<N_NODES / 256, 256>>>(rowsum, inv, N_NODES);
    spmm_csr_kernel<<<N_NODES, 128>>>(C, inv, off, csr_src, csr_w, hi, lo);
    lin_mma_kernel<<<gLin, 256, SIM_SMEM>>>(hi, lo, Whi, Wlo, b, A, nullptr);

    // ---- normalize + split to bf16 hi/lo ----
    l2norm_split_kernel<<<N_NODES, 128>>>(A, hi, lo);

    // ---- similarity: symmetric tiles, mma.sync split-bf16 + relu ----
    int nblk = (N_NODES / SIM_BM);             // 64
    int ntri = nblk * (nblk + 1) / 2;          // 2080
    sim_mma_kernel<<<ntri, 256, SIM_SMEM>>>(hi, lo, out);
}